// round 1
// baseline (speedup 1.0000x reference)
#include <cuda_runtime.h>
#include <cstdint>

#define N_NODES 100000
#define E_EDGES 1600000
#define IN_FEAT 256
#define OUT_FEAT 128

// Scratch for support = x @ W  (100000 x 128 fp32 = 51.2 MB)
__device__ float g_support[(size_t)N_NODES * OUT_FEAT];

// ---------------------------------------------------------------------------
// Kernel 1: initialize out[n][j] = bias[j]   (scatter adds on top)
// ---------------------------------------------------------------------------
__global__ __launch_bounds__(256) void bias_init_kernel(
    const float* __restrict__ bias, float* __restrict__ out)
{
    const int total4 = N_NODES * (OUT_FEAT / 4);   // 3.2M float4
    int idx = blockIdx.x * blockDim.x + threadIdx.x;
    if (idx < total4) {
        int j4 = idx & (OUT_FEAT / 4 - 1);         // OUT_FEAT/4 = 32, pow2
        float4 b = reinterpret_cast<const float4*>(bias)[j4];
        reinterpret_cast<float4*>(out)[idx] = b;
    }
}

// ---------------------------------------------------------------------------
// Kernel 2: support = x @ W
// Tiled fp32 GEMM: BM=64, BN=128, BK=16, 256 threads, 8x4 micro-tile.
// ---------------------------------------------------------------------------
#define BM 64
#define BN 128
#define BK 16
#define TM 8
#define TN 4

__global__ __launch_bounds__(256) void gemm_kernel(
    const float* __restrict__ x,      // [N, 256]
    const float* __restrict__ w,      // [256, 128]
    float* __restrict__ sup)          // [N, 128]
{
    __shared__ float As[BK][BM + 1];  // +1 pad: transposed stores
    __shared__ float Bs[BK][BN];

    const int tid = threadIdx.x;
    const int block_row = blockIdx.x * BM;

    // compute-thread layout: 8 rows x 32 cols of threads
    const int tr = tid >> 5;          // 0..7  -> rows tr*8 .. tr*8+7
    const int tc = tid & 31;          // 0..31 -> cols tc*4 .. tc*4+3

    // A-load layout: one float4 along K per thread (64 rows x 4 float4s)
    const int a_row = tid >> 2;            // 0..63
    const int a_k0  = (tid & 3) * 4;       // 0,4,8,12

    // B-load layout: 512 float4s / 256 threads = 2 each
    const int b_f0 = tid;                  // float4 index, +256 for second

    float acc[TM][TN];
    #pragma unroll
    for (int i = 0; i < TM; i++)
        #pragma unroll
        for (int j = 0; j < TN; j++)
            acc[i][j] = 0.0f;

    for (int kk = 0; kk < IN_FEAT; kk += BK) {
        // --- load A tile (transposed into As[k][m]) ---
        {
            int grow = block_row + a_row;
            float4 av = make_float4(0.f, 0.f, 0.f, 0.f);
            if (grow < N_NODES)
                av = *reinterpret_cast<const float4*>(&x[(size_t)grow * IN_FEAT + kk + a_k0]);
            As[a_k0 + 0][a_row] = av.x;
            As[a_k0 + 1][a_row] = av.y;
            As[a_k0 + 2][a_row] = av.z;
            As[a_k0 + 3][a_row] = av.w;
        }
        // --- load B tile ---
        #pragma unroll
        for (int t = 0; t < 2; t++) {
            int f = b_f0 + t * 256;        // 0..511
            int bk = f >> 5;               // 0..15
            int bn4 = f & 31;              // 0..31
            float4 bv = *reinterpret_cast<const float4*>(&w[(size_t)(kk + bk) * OUT_FEAT + bn4 * 4]);
            *reinterpret_cast<float4*>(&Bs[bk][bn4 * 4]) = bv;
        }
        __syncthreads();

        // --- compute ---
        #pragma unroll
        for (int k = 0; k < BK; k++) {
            float a[TM];
            #pragma unroll
            for (int i = 0; i < TM; i++)
                a[i] = As[k][tr * TM + i];
            float4 bv = *reinterpret_cast<const float4*>(&Bs[k][tc * TN]);
            float b[TN] = {bv.x, bv.y, bv.z, bv.w};
            #pragma unroll
            for (int i = 0; i < TM; i++)
                #pragma unroll
                for (int j = 0; j < TN; j++)
                    acc[i][j] = fmaf(a[i], b[j], acc[i][j]);
        }
        __syncthreads();
    }

    // --- epilogue ---
    #pragma unroll
    for (int i = 0; i < TM; i++) {
        int grow = block_row + tr * TM + i;
        if (grow < N_NODES) {
            float4 v = make_float4(acc[i][0], acc[i][1], acc[i][2], acc[i][3]);
            *reinterpret_cast<float4*>(&sup[(size_t)grow * OUT_FEAT + tc * TN]) = v;
        }
    }
}

// ---------------------------------------------------------------------------
// Kernel 3: COO scatter — warp per edge, vector atomics.
// out[row[e]] += support[col[e]] * ew[e]
// ---------------------------------------------------------------------------
__global__ __launch_bounds__(256) void scatter_kernel(
    const float* __restrict__ sup,
    const float* __restrict__ ew,
    const int* __restrict__ rowi,
    const int* __restrict__ coli,
    float* __restrict__ out)
{
    int gtid = blockIdx.x * blockDim.x + threadIdx.x;
    int e = gtid >> 5;
    int lane = gtid & 31;
    if (e >= E_EDGES) return;

    int c = coli[e];
    int r = rowi[e];
    float wgt = ew[e];

    float4 v = reinterpret_cast<const float4*>(sup + (size_t)c * OUT_FEAT)[lane];
    v.x *= wgt; v.y *= wgt; v.z *= wgt; v.w *= wgt;

    float* dst = out + (size_t)r * OUT_FEAT + lane * 4;
    asm volatile("red.global.add.v4.f32 [%0], {%1, %2, %3, %4};"
                 :: "l"(dst), "f"(v.x), "f"(v.y), "f"(v.z), "f"(v.w)
                 : "memory");
}

// ---------------------------------------------------------------------------
extern "C" void kernel_launch(void* const* d_in, const int* in_sizes, int n_in,
                              void* d_out, int out_size)
{
    const float* x    = (const float*)d_in[0];   // [N, 256]
    const float* w    = (const float*)d_in[1];   // [256, 128]
    const float* bias = (const float*)d_in[2];   // [128]
    const float* ew   = (const float*)d_in[3];   // [E]
    const int*   rowi = (const int*)d_in[4];     // [E]
    const int*   coli = (const int*)d_in[5];     // [E]
    float* out = (float*)d_out;                  // [N, 128]

    float* sup;
    cudaGetSymbolAddress((void**)&sup, g_support);

    // 1) out = bias (broadcast)
    {
        int total4 = N_NODES * (OUT_FEAT / 4);
        int blocks = (total4 + 255) / 256;
        bias_init_kernel<<<blocks, 256>>>(bias, out);
    }
    // 2) support = x @ W
    {
        int blocks = (N_NODES + BM - 1) / BM;
        gemm_kernel<<<blocks, 256>>>(x, w, sup);
    }
    // 3) scatter-add edges
    {
        long long threads = (long long)E_EDGES * 32;
        int blocks = (int)((threads + 255) / 256);
        scatter_kernel<<<blocks, 256>>>(sup, ew, rowi, coli, out);
    }
}

// round 2
// speedup vs baseline: 1.3966x; 1.3966x over previous
#include <cuda_runtime.h>
#include <cstdint>

#define N_NODES 100000
#define E_EDGES 1600000
#define IN_FEAT 256
#define OUT_FEAT 128

#define SCHUNK 256
#define NBLK ((N_NODES + SCHUNK - 1) / SCHUNK)   // 391

// ----- static device scratch (no allocations allowed) -----
__device__ float g_support[(size_t)N_NODES * OUT_FEAT];  // 51.2 MB
__device__ int   g_deg[N_NODES];
__device__ int   g_off[N_NODES + 1];
__device__ int   g_cursor[N_NODES];
__device__ int   g_bsum[NBLK];
__device__ int   g_boff[NBLK];
__device__ int   g_scol[E_EDGES];
__device__ float g_sw[E_EDGES];

// ---------------------------------------------------------------------------
// CSR build step 1: zero degree counters
// ---------------------------------------------------------------------------
__global__ __launch_bounds__(256) void zero_deg_kernel()
{
    int i = blockIdx.x * blockDim.x + threadIdx.x;
    if (i < N_NODES) g_deg[i] = 0;
}

// CSR build step 2: histogram of destination rows
__global__ __launch_bounds__(256) void hist_kernel(const int* __restrict__ rowi)
{
    int e = blockIdx.x * blockDim.x + threadIdx.x;
    if (e < E_EDGES) atomicAdd(&g_deg[rowi[e]], 1);
}

// CSR build step 3a: per-chunk sums
__global__ __launch_bounds__(SCHUNK) void reduce_kernel()
{
    __shared__ int s[SCHUNK];
    int i = blockIdx.x * SCHUNK + threadIdx.x;
    int v = (i < N_NODES) ? g_deg[i] : 0;
    s[threadIdx.x] = v;
    __syncthreads();
    for (int stride = SCHUNK / 2; stride > 0; stride >>= 1) {
        if (threadIdx.x < stride) s[threadIdx.x] += s[threadIdx.x + stride];
        __syncthreads();
    }
    if (threadIdx.x == 0) g_bsum[blockIdx.x] = s[0];
}

// CSR build step 3b: exclusive scan of chunk sums (one block)
__global__ __launch_bounds__(512) void scan_bsums_kernel()
{
    __shared__ int s[512];
    int t = threadIdx.x;
    int v = (t < NBLK) ? g_bsum[t] : 0;
    s[t] = v;
    __syncthreads();
    // Hillis-Steele inclusive scan over 512
    for (int d = 1; d < 512; d <<= 1) {
        int add = (t >= d) ? s[t - d] : 0;
        __syncthreads();
        s[t] += add;
        __syncthreads();
    }
    if (t < NBLK) g_boff[t] = s[t] - v;   // exclusive
}

// CSR build step 3c: per-chunk exclusive scan + add chunk offset
__global__ __launch_bounds__(SCHUNK) void scan_chunk_kernel()
{
    __shared__ int s[SCHUNK];
    int t = threadIdx.x;
    int i = blockIdx.x * SCHUNK + t;
    int d = (i < N_NODES) ? g_deg[i] : 0;
    s[t] = d;
    __syncthreads();
    for (int st = 1; st < SCHUNK; st <<= 1) {
        int add = (t >= st) ? s[t - st] : 0;
        __syncthreads();
        s[t] += add;
        __syncthreads();
    }
    if (i < N_NODES) {
        int off = g_boff[blockIdx.x] + s[t] - d;  // exclusive
        g_off[i] = off;
        g_cursor[i] = off;
        if (i == N_NODES - 1) g_off[N_NODES] = off + d;
    }
}

// CSR build step 4: place edges into row-sorted order
__global__ __launch_bounds__(256) void place_kernel(
    const int* __restrict__ rowi, const int* __restrict__ coli,
    const float* __restrict__ ew)
{
    int e = blockIdx.x * blockDim.x + threadIdx.x;
    if (e < E_EDGES) {
        int r = rowi[e];
        int p = atomicAdd(&g_cursor[r], 1);
        g_scol[p] = coli[e];
        g_sw[p]   = ew[e];
    }
}

// ---------------------------------------------------------------------------
// GEMM: support = x @ W   (BM=64, BN=128, BK=16, 256 thr, 8x4 micro-tile)
// ---------------------------------------------------------------------------
#define BM 64
#define BN 128
#define BK 16
#define TM 8
#define TN 4

__global__ __launch_bounds__(256) void gemm_kernel(
    const float* __restrict__ x,
    const float* __restrict__ w,
    float* __restrict__ sup)
{
    __shared__ float As[BK][BM + 1];
    __shared__ float Bs[BK][BN];

    const int tid = threadIdx.x;
    const int block_row = blockIdx.x * BM;

    const int tr = tid >> 5;
    const int tc = tid & 31;

    const int a_row = tid >> 2;
    const int a_k0  = (tid & 3) * 4;

    float acc[TM][TN];
    #pragma unroll
    for (int i = 0; i < TM; i++)
        #pragma unroll
        for (int j = 0; j < TN; j++)
            acc[i][j] = 0.0f;

    for (int kk = 0; kk < IN_FEAT; kk += BK) {
        {
            int grow = block_row + a_row;
            float4 av = make_float4(0.f, 0.f, 0.f, 0.f);
            if (grow < N_NODES)
                av = *reinterpret_cast<const float4*>(&x[(size_t)grow * IN_FEAT + kk + a_k0]);
            As[a_k0 + 0][a_row] = av.x;
            As[a_k0 + 1][a_row] = av.y;
            As[a_k0 + 2][a_row] = av.z;
            As[a_k0 + 3][a_row] = av.w;
        }
        #pragma unroll
        for (int t = 0; t < 2; t++) {
            int f = tid + t * 256;
            int bk = f >> 5;
            int bn4 = f & 31;
            float4 bv = *reinterpret_cast<const float4*>(&w[(size_t)(kk + bk) * OUT_FEAT + bn4 * 4]);
            *reinterpret_cast<float4*>(&Bs[bk][bn4 * 4]) = bv;
        }
        __syncthreads();

        #pragma unroll
        for (int k = 0; k < BK; k++) {
            float a[TM];
            #pragma unroll
            for (int i = 0; i < TM; i++)
                a[i] = As[k][tr * TM + i];
            float4 bv = *reinterpret_cast<const float4*>(&Bs[k][tc * TN]);
            float b[TN] = {bv.x, bv.y, bv.z, bv.w};
            #pragma unroll
            for (int i = 0; i < TM; i++)
                #pragma unroll
                for (int j = 0; j < TN; j++)
                    acc[i][j] = fmaf(a[i], b[j], acc[i][j]);
        }
        __syncthreads();
    }

    #pragma unroll
    for (int i = 0; i < TM; i++) {
        int grow = block_row + tr * TM + i;
        if (grow < N_NODES) {
            float4 v = make_float4(acc[i][0], acc[i][1], acc[i][2], acc[i][3]);
            *reinterpret_cast<float4*>(&sup[(size_t)grow * OUT_FEAT + tc * TN]) = v;
        }
    }
}

// ---------------------------------------------------------------------------
// Gather: warp per node. out[n] = bias + sum_e w_e * support[col_e]
// No atomics: each output row written exactly once.
// ---------------------------------------------------------------------------
__global__ __launch_bounds__(256) void gather_kernel(
    const float* __restrict__ sup,
    const float* __restrict__ bias,
    float* __restrict__ out)
{
    int gtid = blockIdx.x * blockDim.x + threadIdx.x;
    int n = gtid >> 5;
    int lane = gtid & 31;
    if (n >= N_NODES) return;

    int o0 = g_off[n];
    int o1 = g_off[n + 1];

    float4 acc = reinterpret_cast<const float4*>(bias)[lane];

    int e = o0;
    // 2-way unroll for MLP
    for (; e + 1 < o1; e += 2) {
        int   c0 = g_scol[e],     c1 = g_scol[e + 1];
        float w0 = g_sw[e],       w1 = g_sw[e + 1];
        float4 v0 = reinterpret_cast<const float4*>(sup + (size_t)c0 * OUT_FEAT)[lane];
        float4 v1 = reinterpret_cast<const float4*>(sup + (size_t)c1 * OUT_FEAT)[lane];
        acc.x = fmaf(v0.x, w0, acc.x);
        acc.y = fmaf(v0.y, w0, acc.y);
        acc.z = fmaf(v0.z, w0, acc.z);
        acc.w = fmaf(v0.w, w0, acc.w);
        acc.x = fmaf(v1.x, w1, acc.x);
        acc.y = fmaf(v1.y, w1, acc.y);
        acc.z = fmaf(v1.z, w1, acc.z);
        acc.w = fmaf(v1.w, w1, acc.w);
    }
    if (e < o1) {
        int   c0 = g_scol[e];
        float w0 = g_sw[e];
        float4 v0 = reinterpret_cast<const float4*>(sup + (size_t)c0 * OUT_FEAT)[lane];
        acc.x = fmaf(v0.x, w0, acc.x);
        acc.y = fmaf(v0.y, w0, acc.y);
        acc.z = fmaf(v0.z, w0, acc.z);
        acc.w = fmaf(v0.w, w0, acc.w);
    }

    reinterpret_cast<float4*>(out + (size_t)n * OUT_FEAT)[lane] = acc;
}

// ---------------------------------------------------------------------------
extern "C" void kernel_launch(void* const* d_in, const int* in_sizes, int n_in,
                              void* d_out, int out_size)
{
    const float* x    = (const float*)d_in[0];
    const float* w    = (const float*)d_in[1];
    const float* bias = (const float*)d_in[2];
    const float* ew   = (const float*)d_in[3];
    const int*   rowi = (const int*)d_in[4];
    const int*   coli = (const int*)d_in[5];
    float* out = (float*)d_out;

    float* sup;
    cudaGetSymbolAddress((void**)&sup, g_support);

    // --- CSR build (counting sort by destination row) ---
    zero_deg_kernel<<<(N_NODES + 255) / 256, 256>>>();
    hist_kernel<<<(E_EDGES + 255) / 256, 256>>>(rowi);
    reduce_kernel<<<NBLK, SCHUNK>>>();
    scan_bsums_kernel<<<1, 512>>>();
    scan_chunk_kernel<<<NBLK, SCHUNK>>>();
    place_kernel<<<(E_EDGES + 255) / 256, 256>>>(rowi, coli, ew);

    // --- support = x @ W ---
    gemm_kernel<<<(N_NODES + BM - 1) / BM, 256>>>(x, w, sup);

    // --- out = bias + gather-accumulate ---
    {
        long long threads = (long long)N_NODES * 32;
        int blocks = (int)((threads + 255) / 256);
        gather_kernel<<<blocks, 256>>>(sup, bias, out);
    }
}